// round 14
// baseline (speedup 1.0000x reference)
#include <cuda_runtime.h>
#include <math.h>

#define Hdim 128
#define NMAX 65536
#define EMAX 1048576

// ---------------- scratch (no cudaMalloc allowed) ----------------
__device__ float g_h[NMAX * Hdim];
__device__ float g_agg[NMAX * Hdim];
__device__ float g_x[NMAX * 3];
__device__ float g_coord[NMAX * 3];
__device__ float g_deg[NMAX];
__device__ float g_eps[NMAX * 3];
__device__ int g_ei32[2 * EMAX];  // normalized edge indices (row | col)
__device__ int g_mode;            // 1 = input is int64, 0 = input is int32

__device__ __forceinline__ float silu_f(float v) { return v / (1.0f + __expf(-v)); }

// ---------------- edge-index dtype normalization ----------------
// The dataset's edge_index may be int64 (as written in the reference) or int32
// (JAX default x64-disabled). Detect on device: true int64 indices (< N) have
// zero high words; int32 data parsed as int64 has random nonzero high words
// (each high word is itself an index in [0,N), zero with prob ~1/N).
__global__ void detect_kernel(const void* __restrict__ p, int count) {
    if (threadIdx.x == 0 && blockIdx.x == 0) {
        const long long* q = (const long long*)p;
        int n = 64;
        if (n > count / 2) n = count / 2;  // never read past count*4 bytes
        int is64 = 1;
        for (int i = 0; i < n; i++) {
            unsigned long long v = (unsigned long long)q[i];
            if (v >> 32) { is64 = 0; break; }
        }
        g_mode = is64;
    }
}

// Normalize to int32 AND clamp to [0, N-1]: if the dtype detection is ever
// wrong, this turns a wild-address trap into a finite wrong answer (rel_err),
// which is strictly more diagnostic than a crash.
__global__ void convert_kernel(const void* __restrict__ p, int count, int N) {
    int i = blockIdx.x * blockDim.x + threadIdx.x;
    if (i < count) {
        int v;
        if (g_mode) v = (int)((const long long*)p)[i];
        else        v = ((const int*)p)[i];
        if (v < 0) v = 0;
        if (v >= N) v = N - 1;
        g_ei32[i] = v;
    }
}

// ---------------- init / clear kernels (graph-safe) ----------------
__global__ void init_kernel(int N, const float* __restrict__ x_in) {
    int i = blockIdx.x * blockDim.x + threadIdx.x;
    if (i < N) {
        g_deg[i] = 0.0f;
        g_eps[i * 3 + 0] = 0.0f; g_eps[i * 3 + 1] = 0.0f; g_eps[i * 3 + 2] = 0.0f;
        g_x[i * 3 + 0] = x_in[i * 3 + 0];
        g_x[i * 3 + 1] = x_in[i * 3 + 1];
        g_x[i * 3 + 2] = x_in[i * 3 + 2];
    }
}

// zero agg (N*128 floats) and coord (N*3 floats)
__global__ void clear_layer_kernel(int N) {
    int i = blockIdx.x * blockDim.x + threadIdx.x;
    int n4 = N * 32;  // N*128 floats = N*32 float4
    if (i < n4) ((float4*)g_agg)[i] = make_float4(0.f, 0.f, 0.f, 0.f);
    if (i < N) {
        g_coord[i * 3 + 0] = 0.0f; g_coord[i * 3 + 1] = 0.0f; g_coord[i * 3 + 2] = 0.0f;
    }
}

// ---------------- degree kernel ----------------
__global__ void deg_kernel(const int* __restrict__ ecol, int E) {
    int e = blockIdx.x * blockDim.x + threadIdx.x;
    if (e < E) atomicAdd(&g_deg[ecol[e]], 1.0f);
}

// ---------------- shared-memory tiled GEMM helper ----------------
// 256 threads. tx = tid&15 -> 8 output features (tx*8..tx*8+7).
// ty = tid>>4 -> RPT rows (ty*RPT..ty*RPT+RPT-1).
// sIn: [rows][S] in shared. gW: [K][128] in global (L2-resident), staged 32 rows
// at a time through sW (32*128 floats). K must be a multiple of 32.
template <int RPT>
__device__ __forceinline__ void gemm_accum(int K, int S, const float* sIn,
                                           const float* gW, float* sW,
                                           float (&acc)[RPT][8], int tx, int ty,
                                           int tid) {
    for (int kk = 0; kk < K; kk += 32) {
        const float4* src = (const float4*)(gW + (size_t)kk * Hdim);
        float4* dst = (float4*)sW;
#pragma unroll
        for (int t = 0; t < 4; t++) dst[tid + t * 256] = src[tid + t * 256];
        __syncthreads();
#pragma unroll
        for (int k4 = 0; k4 < 32; k4 += 4) {
            float av[RPT][4];
#pragma unroll
            for (int r = 0; r < RPT; r++) {
                float4 a = *(const float4*)&sIn[(ty * RPT + r) * S + kk + k4];
                av[r][0] = a.x; av[r][1] = a.y; av[r][2] = a.z; av[r][3] = a.w;
            }
#pragma unroll
            for (int j = 0; j < 4; j++) {
                float4 w0 = *(const float4*)&sW[(k4 + j) * Hdim + tx * 8];
                float4 w1 = *(const float4*)&sW[(k4 + j) * Hdim + tx * 8 + 4];
#pragma unroll
                for (int r = 0; r < RPT; r++) {
                    float c = av[r][j];
                    acc[r][0] = fmaf(c, w0.x, acc[r][0]);
                    acc[r][1] = fmaf(c, w0.y, acc[r][1]);
                    acc[r][2] = fmaf(c, w0.z, acc[r][2]);
                    acc[r][3] = fmaf(c, w0.w, acc[r][3]);
                    acc[r][4] = fmaf(c, w1.x, acc[r][4]);
                    acc[r][5] = fmaf(c, w1.y, acc[r][5]);
                    acc[r][6] = fmaf(c, w1.z, acc[r][6]);
                    acc[r][7] = fmaf(c, w1.w, acc[r][7]);
                }
            }
        }
        __syncthreads();
    }
}

// ---------------- embedding: h = h_in @ W_emb + b_emb ----------------
// 64 nodes/block, 256 threads. smem: s_in 64*68, s_w 32*128
__global__ __launch_bounds__(256) void emb_kernel(int N,
                                                  const float* __restrict__ hin,
                                                  const float* __restrict__ W,
                                                  const float* __restrict__ b) {
    extern __shared__ float sm[];
    float* s_in = sm;            // 64 x 68 (64 used)
    float* s_w = s_in + 64 * 68; // 32 x 128
    int tid = threadIdx.x;
    int tx = tid & 15, ty = tid >> 4;
    int n0 = blockIdx.x * 64;
    {
        int nl = tid >> 2, q = tid & 3;
        int n = n0 + nl; if (n >= N) n = N - 1;
        const float4* hp = (const float4*)(hin + (size_t)n * 64) + q * 4;
        float4* d0 = (float4*)(s_in + nl * 68 + q * 16);
#pragma unroll
        for (int t = 0; t < 4; t++) d0[t] = hp[t];
    }
    __syncthreads();
    float acc[4][8];
    {
        float bb[8];
#pragma unroll
        for (int j = 0; j < 8; j++) bb[j] = b[tx * 8 + j];
#pragma unroll
        for (int r = 0; r < 4; r++)
#pragma unroll
            for (int j = 0; j < 8; j++) acc[r][j] = bb[j];
    }
    gemm_accum<4>(64, 68, s_in, W, s_w, acc, tx, ty, tid);
#pragma unroll
    for (int r = 0; r < 4; r++) {
        int n = n0 + ty * 4 + r;
        if (n < N) {
#pragma unroll
            for (int j = 0; j < 8; j++) g_h[(size_t)n * Hdim + tx * 8 + j] = acc[r][j];
        }
    }
}

// ---------------- fused per-layer edge kernel ----------------
// 64 edges/block, 256 threads.
__global__ __launch_bounds__(256) void edge_layer_kernel(
    const int* __restrict__ erow, const int* __restrict__ ecol, int E,
    const float* __restrict__ Wm1, const float* __restrict__ bm1,
    const float* __restrict__ Wm2, const float* __restrict__ bm2,
    const float* __restrict__ Wc1, const float* __restrict__ bc1,
    const float* __restrict__ Wc2) {
    extern __shared__ float sm[];
    float* s_in = sm;                 // 64 x 260 (hr|hc|dist)
    float* s_w = s_in + 64 * 260;     // 32 x 128
    float* s_b1 = s_w + 32 * Hdim;    // 64 x 128
    float* s_b2 = s_b1 + 64 * Hdim;   // 64 x 128
    float* s_rel = s_b2 + 64 * Hdim;  // 64 x 4
    float* s_cm = s_rel + 256;        // 64
    int* s_col = (int*)(s_cm + 64);   // 64

    int tid = threadIdx.x;
    int tx = tid & 15, ty = tid >> 4;
    int e0 = blockIdx.x * 64;

    {
        int el = tid >> 2, q = tid & 3;
        int ee = e0 + el; if (ee >= E) ee = E - 1;
        int r = erow[ee], c = ecol[ee];
        const float4* hr = (const float4*)(g_h + (size_t)r * Hdim) + q * 8;
        const float4* hc = (const float4*)(g_h + (size_t)c * Hdim) + q * 8;
        float4* d0 = (float4*)(s_in + el * 260 + q * 32);
        float4* d1 = (float4*)(s_in + el * 260 + 128 + q * 32);
#pragma unroll
        for (int t = 0; t < 8; t++) { d0[t] = hr[t]; d1[t] = hc[t]; }
    }
    if (tid < 64) {
        int ee = e0 + tid; bool valid = (ee < E); if (!valid) ee = E - 1;
        int r = erow[ee], c = ecol[ee];
        float rx = g_x[r * 3 + 0] - g_x[c * 3 + 0];
        float ry = g_x[r * 3 + 1] - g_x[c * 3 + 1];
        float rz = g_x[r * 3 + 2] - g_x[c * 3 + 2];
        float dist = sqrtf(rx * rx + ry * ry + rz * rz);
        s_rel[tid * 4 + 0] = rx; s_rel[tid * 4 + 1] = ry;
        s_rel[tid * 4 + 2] = rz; s_rel[tid * 4 + 3] = dist;
        s_cm[tid] = 0.0f;
        s_col[tid] = valid ? c : -1;
    }
    __syncthreads();

    float acc[4][8];
    // --- GEMM1: out1 = silu(mi @ Wm1 + bm1), K = 257 (dist row handled here)
    {
        float bb[8], wl[8];
#pragma unroll
        for (int j = 0; j < 8; j++) {
            bb[j] = bm1[tx * 8 + j];
            wl[j] = Wm1[256 * Hdim + tx * 8 + j];
        }
#pragma unroll
        for (int r = 0; r < 4; r++) {
            float dist = s_rel[(ty * 4 + r) * 4 + 3];
#pragma unroll
            for (int j = 0; j < 8; j++) acc[r][j] = fmaf(dist, wl[j], bb[j]);
        }
    }
    gemm_accum<4>(256, 260, s_in, Wm1, s_w, acc, tx, ty, tid);
#pragma unroll
    for (int r = 0; r < 4; r++) {
        float4 v0, v1;
        v0.x = silu_f(acc[r][0]); v0.y = silu_f(acc[r][1]);
        v0.z = silu_f(acc[r][2]); v0.w = silu_f(acc[r][3]);
        v1.x = silu_f(acc[r][4]); v1.y = silu_f(acc[r][5]);
        v1.z = silu_f(acc[r][6]); v1.w = silu_f(acc[r][7]);
        *(float4*)&s_b1[(ty * 4 + r) * Hdim + tx * 8] = v0;
        *(float4*)&s_b1[(ty * 4 + r) * Hdim + tx * 8 + 4] = v1;
    }
    // --- GEMM2: m = silu(out1 @ Wm2 + bm2), scatter into agg
    {
        float bb[8];
#pragma unroll
        for (int j = 0; j < 8; j++) bb[j] = bm2[tx * 8 + j];
#pragma unroll
        for (int r = 0; r < 4; r++)
#pragma unroll
            for (int j = 0; j < 8; j++) acc[r][j] = bb[j];
    }
    gemm_accum<4>(128, 128, s_b1, Wm2, s_w, acc, tx, ty, tid);
#pragma unroll
    for (int r = 0; r < 4; r++) {
        float mv[8];
#pragma unroll
        for (int j = 0; j < 8; j++) mv[j] = silu_f(acc[r][j]);
        float4 v0 = {mv[0], mv[1], mv[2], mv[3]};
        float4 v1 = {mv[4], mv[5], mv[6], mv[7]};
        *(float4*)&s_b2[(ty * 4 + r) * Hdim + tx * 8] = v0;
        *(float4*)&s_b2[(ty * 4 + r) * Hdim + tx * 8 + 4] = v1;
        int c = s_col[ty * 4 + r];
        if (c >= 0) {
            float* base = g_agg + (size_t)c * Hdim + tx * 8;
#pragma unroll
            for (int j = 0; j < 8; j++) atomicAdd(base + j, mv[j]);
        }
    }
    // --- GEMM3: c1 = silu(m @ Wc1 + bc1); coord_mult = tanh(c1 . Wc2)
    {
        float bb[8];
#pragma unroll
        for (int j = 0; j < 8; j++) bb[j] = bc1[tx * 8 + j];
#pragma unroll
        for (int r = 0; r < 4; r++)
#pragma unroll
            for (int j = 0; j < 8; j++) acc[r][j] = bb[j];
    }
    gemm_accum<4>(128, 128, s_b2, Wc1, s_w, acc, tx, ty, tid);
    {
        float wc[8];
#pragma unroll
        for (int j = 0; j < 8; j++) wc[j] = Wc2[tx * 8 + j];
#pragma unroll
        for (int r = 0; r < 4; r++) {
            float p = 0.0f;
#pragma unroll
            for (int j = 0; j < 8; j++) p = fmaf(silu_f(acc[r][j]), wc[j], p);
            atomicAdd(&s_cm[ty * 4 + r], p);
        }
    }
    __syncthreads();
    if (tid < 64) {
        int c = s_col[tid];
        if (c >= 0) {
            float cm = tanhf(s_cm[tid]);
            float inv = 1.0f / (s_rel[tid * 4 + 3] + 1e-8f);
            float s = cm * inv;
#pragma unroll
            for (int d = 0; d < 3; d++)
                atomicAdd(&g_coord[(size_t)c * 3 + d], s * s_rel[tid * 4 + d]);
        }
    }
}

// ---------------- per-layer node kernel ----------------
// 32 nodes/block, 256 threads.
__global__ __launch_bounds__(256) void node_layer_kernel(
    int N, const float* __restrict__ Wn1, const float* __restrict__ bn1,
    const float* __restrict__ Wn2, const float* __restrict__ bn2,
    const float* __restrict__ lng, const float* __restrict__ lnb) {
    extern __shared__ float sm[];
    float* s_nu = sm;              // 32 x 256 (h|agg), later holds pre-LN values
    float* s_w = s_nu + 32 * 256;  // 32 x 128
    float* s_t = s_w + 32 * Hdim;  // 32 x 132
    int tid = threadIdx.x;
    int tx = tid & 15, ty = tid >> 4;
    int n0 = blockIdx.x * 32;

    if (tid < 32) {
        int n = n0 + tid;
        if (n < N) {
            float inv = 1.0f / (g_deg[n] + 1.0f);
#pragma unroll
            for (int d = 0; d < 3; d++)
                g_x[(size_t)n * 3 + d] += g_coord[(size_t)n * 3 + d] * inv;
        }
    }
    {
        int nl = tid >> 3, p = tid & 7;
        int n = n0 + nl; if (n >= N) n = N - 1;
        const float4* hp = (const float4*)(g_h + (size_t)n * Hdim) + p * 4;
        const float4* ap = (const float4*)(g_agg + (size_t)n * Hdim) + p * 4;
        float4* d0 = (float4*)(s_nu + nl * 256 + p * 16);
        float4* d1 = (float4*)(s_nu + nl * 256 + 128 + p * 16);
#pragma unroll
        for (int t = 0; t < 4; t++) { d0[t] = hp[t]; d1[t] = ap[t]; }
    }
    __syncthreads();

    float acc[2][8];
    {
        float bb[8];
#pragma unroll
        for (int j = 0; j < 8; j++) bb[j] = bn1[tx * 8 + j];
#pragma unroll
        for (int r = 0; r < 2; r++)
#pragma unroll
            for (int j = 0; j < 8; j++) acc[r][j] = bb[j];
    }
    gemm_accum<2>(256, 256, s_nu, Wn1, s_w, acc, tx, ty, tid);
#pragma unroll
    for (int r = 0; r < 2; r++) {
        float4 v0, v1;
        v0.x = silu_f(acc[r][0]); v0.y = silu_f(acc[r][1]);
        v0.z = silu_f(acc[r][2]); v0.w = silu_f(acc[r][3]);
        v1.x = silu_f(acc[r][4]); v1.y = silu_f(acc[r][5]);
        v1.z = silu_f(acc[r][6]); v1.w = silu_f(acc[r][7]);
        *(float4*)&s_t[(ty * 2 + r) * 132 + tx * 8] = v0;
        *(float4*)&s_t[(ty * 2 + r) * 132 + tx * 8 + 4] = v1;
    }
    {
        float bb[8];
#pragma unroll
        for (int j = 0; j < 8; j++) bb[j] = bn2[tx * 8 + j];
#pragma unroll
        for (int r = 0; r < 2; r++)
#pragma unroll
            for (int j = 0; j < 8; j++) acc[r][j] = bb[j];
    }
    gemm_accum<2>(128, 132, s_t, Wn2, s_w, acc, tx, ty, tid);
    // v = h_old + d, stored in-place over the h half of s_nu
#pragma unroll
    for (int r = 0; r < 2; r++)
#pragma unroll
        for (int j = 0; j < 8; j++)
            s_nu[(ty * 2 + r) * 256 + tx * 8 + j] += acc[r][j];
    __syncthreads();
    // LayerNorm: warp w handles nodes w*4..w*4+3
    int wid = tid >> 5, lane = tid & 31;
#pragma unroll
    for (int k = 0; k < 4; k++) {
        int nl = wid * 4 + k;
        int n = n0 + nl;
        float v[4];
#pragma unroll
        for (int t = 0; t < 4; t++) v[t] = s_nu[nl * 256 + lane * 4 + t];
        float s = v[0] + v[1] + v[2] + v[3];
#pragma unroll
        for (int o = 16; o > 0; o >>= 1) s += __shfl_xor_sync(0xffffffffu, s, o);
        float mu = s * (1.0f / 128.0f);
        float q = 0.0f;
#pragma unroll
        for (int t = 0; t < 4; t++) { float d = v[t] - mu; q = fmaf(d, d, q); }
#pragma unroll
        for (int o = 16; o > 0; o >>= 1) q += __shfl_xor_sync(0xffffffffu, q, o);
        float rs = rsqrtf(q * (1.0f / 128.0f) + 1e-5f);
        if (n < N) {
#pragma unroll
            for (int t = 0; t < 4; t++) {
                int f = lane * 4 + t;
                g_h[(size_t)n * Hdim + f] = (v[t] - mu) * rs * lng[f] + lnb[f];
            }
        }
    }
}

// ---------------- epsilon edge head ----------------
__global__ __launch_bounds__(256) void eps_edge_kernel(
    const int* __restrict__ erow, const int* __restrict__ ecol, int E,
    const float* __restrict__ Wem1, const float* __restrict__ bem1,
    const float* __restrict__ Wem2, const float* __restrict__ bem2,
    const float* __restrict__ Wec1, const float* __restrict__ bec1,
    const float* __restrict__ Wec2, const float* __restrict__ bec2) {
    extern __shared__ float sm[];
    float* s_in = sm;                 // 64 x 260
    float* s_w = s_in + 64 * 260;     // 32 x 128
    float* s_b1 = s_w + 32 * Hdim;    // 64 x 128
    float* s_b2 = s_b1 + 64 * Hdim;   // 64 x 128
    float* s_rel = s_b2 + 64 * Hdim;  // 64 x 4
    float* s_eps = s_rel + 256;       // 64 x 3
    int* s_col = (int*)(s_eps + 192); // 64

    int tid = threadIdx.x;
    int tx = tid & 15, ty = tid >> 4;
    int e0 = blockIdx.x * 64;

    {
        int el = tid >> 2, q = tid & 3;
        int ee = e0 + el; if (ee >= E) ee = E - 1;
        int r = erow[ee], c = ecol[ee];
        const float4* hr = (const float4*)(g_h + (size_t)r * Hdim) + q * 8;
        const float4* hc = (const float4*)(g_h + (size_t)c * Hdim) + q * 8;
        float4* d0 = (float4*)(s_in + el * 260 + q * 32);
        float4* d1 = (float4*)(s_in + el * 260 + 128 + q * 32);
#pragma unroll
        for (int t = 0; t < 8; t++) { d0[t] = hr[t]; d1[t] = hc[t]; }
    }
    if (tid < 64) {
        int ee = e0 + tid; bool valid = (ee < E); if (!valid) ee = E - 1;
        int r = erow[ee], c = ecol[ee];
        float rx = g_x[r * 3 + 0] - g_x[c * 3 + 0];
        float ry = g_x[r * 3 + 1] - g_x[c * 3 + 1];
        float rz = g_x[r * 3 + 2] - g_x[c * 3 + 2];
        float dist = sqrtf(rx * rx + ry * ry + rz * rz);
        s_rel[tid * 4 + 0] = rx; s_rel[tid * 4 + 1] = ry;
        s_rel[tid * 4 + 2] = rz; s_rel[tid * 4 + 3] = dist;
        s_eps[tid * 3 + 0] = 0.0f; s_eps[tid * 3 + 1] = 0.0f; s_eps[tid * 3 + 2] = 0.0f;
        s_col[tid] = valid ? c : -1;
    }
    __syncthreads();

    float acc[4][8];
    // mi = [hr(128) | hc(128) | rel(3) | dist(1)], K = 260
    {
        float bb[8], w0[8], w1[8], w2[8], w3[8];
#pragma unroll
        for (int j = 0; j < 8; j++) {
            bb[j] = bem1[tx * 8 + j];
            w0[j] = Wem1[256 * Hdim + tx * 8 + j];
            w1[j] = Wem1[257 * Hdim + tx * 8 + j];
            w2[j] = Wem1[258 * Hdim + tx * 8 + j];
            w3[j] = Wem1[259 * Hdim + tx * 8 + j];
        }
#pragma unroll
        for (int r = 0; r < 4; r++) {
            int e = ty * 4 + r;
            float rx = s_rel[e * 4 + 0], ry = s_rel[e * 4 + 1];
            float rz = s_rel[e * 4 + 2], dd = s_rel[e * 4 + 3];
#pragma unroll
            for (int j = 0; j < 8; j++) {
                float a = fmaf(rx, w0[j], bb[j]);
                a = fmaf(ry, w1[j], a);
                a = fmaf(rz, w2[j], a);
                acc[r][j] = fmaf(dd, w3[j], a);
            }
        }
    }
    gemm_accum<4>(256, 260, s_in, Wem1, s_w, acc, tx, ty, tid);
#pragma unroll
    for (int r = 0; r < 4; r++) {
        float4 v0, v1;
        v0.x = silu_f(acc[r][0]); v0.y = silu_f(acc[r][1]);
        v0.z = silu_f(acc[r][2]); v0.w = silu_f(acc[r][3]);
        v1.x = silu_f(acc[r][4]); v1.y = silu_f(acc[r][5]);
        v1.z = silu_f(acc[r][6]); v1.w = silu_f(acc[r][7]);
        *(float4*)&s_b1[(ty * 4 + r) * Hdim + tx * 8] = v0;
        *(float4*)&s_b1[(ty * 4 + r) * Hdim + tx * 8 + 4] = v1;
    }
    {
        float bb[8];
#pragma unroll
        for (int j = 0; j < 8; j++) bb[j] = bem2[tx * 8 + j];
#pragma unroll
        for (int r = 0; r < 4; r++)
#pragma unroll
            for (int j = 0; j < 8; j++) acc[r][j] = bb[j];
    }
    gemm_accum<4>(128, 128, s_b1, Wem2, s_w, acc, tx, ty, tid);
#pragma unroll
    for (int r = 0; r < 4; r++) {
        float4 v0, v1;
        v0.x = silu_f(acc[r][0]); v0.y = silu_f(acc[r][1]);
        v0.z = silu_f(acc[r][2]); v0.w = silu_f(acc[r][3]);
        v1.x = silu_f(acc[r][4]); v1.y = silu_f(acc[r][5]);
        v1.z = silu_f(acc[r][6]); v1.w = silu_f(acc[r][7]);
        *(float4*)&s_b2[(ty * 4 + r) * Hdim + tx * 8] = v0;
        *(float4*)&s_b2[(ty * 4 + r) * Hdim + tx * 8 + 4] = v1;
    }
    {
        float bb[8];
#pragma unroll
        for (int j = 0; j < 8; j++) bb[j] = bec1[tx * 8 + j];
#pragma unroll
        for (int r = 0; r < 4; r++)
#pragma unroll
            for (int j = 0; j < 8; j++) acc[r][j] = bb[j];
    }
    gemm_accum<4>(128, 128, s_b2, Wec1, s_w, acc, tx, ty, tid);
    {
        float wr[8][3];
#pragma unroll
        for (int j = 0; j < 8; j++)
#pragma unroll
            for (int d = 0; d < 3; d++) wr[j][d] = Wec2[(tx * 8 + j) * 3 + d];
#pragma unroll
        for (int r = 0; r < 4; r++) {
            float p0 = 0.0f, p1 = 0.0f, p2 = 0.0f;
#pragma unroll
            for (int j = 0; j < 8; j++) {
                float t = silu_f(acc[r][j]);
                p0 = fmaf(t, wr[j][0], p0);
                p1 = fmaf(t, wr[j][1], p1);
                p2 = fmaf(t, wr[j][2], p2);
            }
            atomicAdd(&s_eps[(ty * 4 + r) * 3 + 0], p0);
            atomicAdd(&s_eps[(ty * 4 + r) * 3 + 1], p1);
            atomicAdd(&s_eps[(ty * 4 + r) * 3 + 2], p2);
        }
    }
    __syncthreads();
    if (tid < 64) {
        int c = s_col[tid];
        if (c >= 0) {
#pragma unroll
            for (int d = 0; d < 3; d++)
                atomicAdd(&g_eps[(size_t)c * 3 + d], s_eps[tid * 3 + d] + bec2[d]);
        }
    }
}

// ---------------- final node head + output writeback ----------------
__global__ __launch_bounds__(256) void final_kernel(int N, float* __restrict__ out,
                                                    const float* __restrict__ Wh1,
                                                    const float* __restrict__ bh1,
                                                    const float* __restrict__ Wh2,
                                                    const float* __restrict__ bh2) {
    extern __shared__ float sm[];
    float* s_hx = sm;              // 32 x 132 (h|x)
    float* s_w = s_hx + 32 * 132;  // 32 x 128
    float* s_o = s_w + 32 * Hdim;  // 32 x 3
    int tid = threadIdx.x;
    int tx = tid & 15, ty = tid >> 4;
    int n0 = blockIdx.x * 32;

    {
        int nl = tid >> 3, p = tid & 7;
        int n = n0 + nl; bool v = (n < N); int nn = v ? n : N - 1;
        const float4* hp = (const float4*)(g_h + (size_t)nn * Hdim) + p * 4;
        float4* d0 = (float4*)(s_hx + nl * 132 + p * 16);
        float4* o = (float4*)(out + (size_t)nn * Hdim) + p * 4;
#pragma unroll
        for (int t = 0; t < 4; t++) { float4 vv = hp[t]; d0[t] = vv; if (v) o[t] = vv; }
    }
    if (tid < 32) {
        int n = n0 + tid; bool v = (n < N); int nn = v ? n : N - 1;
#pragma unroll
        for (int d = 0; d < 3; d++) {
            float xv = g_x[(size_t)nn * 3 + d];
            s_hx[tid * 132 + 128 + d] = xv;
            if (v) out[(size_t)N * Hdim + (size_t)nn * 3 + d] = xv;
        }
        s_o[tid * 3 + 0] = 0.0f; s_o[tid * 3 + 1] = 0.0f; s_o[tid * 3 + 2] = 0.0f;
    }
    __syncthreads();

    float acc[2][8];
    {
        float bb[8], w0[8], w1[8], w2[8];
#pragma unroll
        for (int j = 0; j < 8; j++) {
            bb[j] = bh1[tx * 8 + j];
            w0[j] = Wh1[128 * Hdim + tx * 8 + j];
            w1[j] = Wh1[129 * Hdim + tx * 8 + j];
            w2[j] = Wh1[130 * Hdim + tx * 8 + j];
        }
#pragma unroll
        for (int r = 0; r < 2; r++) {
            int nl = ty * 2 + r;
            float x0 = s_hx[nl * 132 + 128];
            float x1 = s_hx[nl * 132 + 129];
            float x2 = s_hx[nl * 132 + 130];
#pragma unroll
            for (int j = 0; j < 8; j++) {
                float a = fmaf(x0, w0[j], bb[j]);
                a = fmaf(x1, w1[j], a);
                acc[r][j] = fmaf(x2, w2[j], a);
            }
        }
    }
    gemm_accum<2>(128, 132, s_hx, Wh1, s_w, acc, tx, ty, tid);
    {
        float wr[8][3];
#pragma unroll
        for (int j = 0; j < 8; j++)
#pragma unroll
            for (int d = 0; d < 3; d++) wr[j][d] = Wh2[(tx * 8 + j) * 3 + d];
#pragma unroll
        for (int r = 0; r < 2; r++) {
            float p0 = 0.0f, p1 = 0.0f, p2 = 0.0f;
#pragma unroll
            for (int j = 0; j < 8; j++) {
                float t = silu_f(acc[r][j]);
                p0 = fmaf(t, wr[j][0], p0);
                p1 = fmaf(t, wr[j][1], p1);
                p2 = fmaf(t, wr[j][2], p2);
            }
            atomicAdd(&s_o[(ty * 2 + r) * 3 + 0], p0);
            atomicAdd(&s_o[(ty * 2 + r) * 3 + 1], p1);
            atomicAdd(&s_o[(ty * 2 + r) * 3 + 2], p2);
        }
    }
    __syncthreads();
    if (tid < 96) {
        int nl = tid / 3, d = tid % 3;
        int n = n0 + nl;
        if (n < N)
            out[(size_t)N * Hdim + (size_t)N * 3 + (size_t)n * 3 + d] =
                g_eps[(size_t)n * 3 + d] + s_o[tid] + bh2[d];
    }
}

// ---------------- host launcher ----------------
#define SMEM_EDGE ((64 * 260 + 32 * 128 + 64 * 128 + 64 * 128 + 64 * 4 + 64 + 64) * 4)
#define SMEM_EPS ((64 * 260 + 32 * 128 + 64 * 128 + 64 * 128 + 64 * 4 + 64 * 3 + 64) * 4)
#define SMEM_NODE ((32 * 256 + 32 * 128 + 32 * 132) * 4)
#define SMEM_EMB ((64 * 68 + 32 * 128) * 4)
#define SMEM_FINAL ((32 * 132 + 32 * 128 + 32 * 3) * 4)

extern "C" void kernel_launch(void* const* d_in, const int* in_sizes, int n_in,
                              void* d_out, int out_size) {
    const float* h_in = (const float*)d_in[0];
    const float* x_in = (const float*)d_in[1];
    const void* ei_raw = d_in[2];
    const float* W_emb = (const float*)d_in[3];
    const float* b_emb = (const float*)d_in[4];
    const float* Wm1 = (const float*)d_in[5];
    const float* bm1 = (const float*)d_in[6];
    const float* Wm2 = (const float*)d_in[7];
    const float* bm2 = (const float*)d_in[8];
    const float* Wc1 = (const float*)d_in[9];
    const float* bc1 = (const float*)d_in[10];
    const float* Wc2 = (const float*)d_in[11];
    const float* Wn1 = (const float*)d_in[12];
    const float* bn1 = (const float*)d_in[13];
    const float* Wn2 = (const float*)d_in[14];
    const float* bn2 = (const float*)d_in[15];
    const float* lng = (const float*)d_in[16];
    const float* lnb = (const float*)d_in[17];
    const float* Wem1 = (const float*)d_in[18];
    const float* bem1 = (const float*)d_in[19];
    const float* Wem2 = (const float*)d_in[20];
    const float* bem2 = (const float*)d_in[21];
    const float* Wec1 = (const float*)d_in[22];
    const float* bec1 = (const float*)d_in[23];
    const float* Wec2 = (const float*)d_in[24];
    const float* bec2 = (const float*)d_in[25];
    const float* Wh1 = (const float*)d_in[26];
    const float* bh1 = (const float*)d_in[27];
    const float* Wh2 = (const float*)d_in[28];
    const float* bh2 = (const float*)d_in[29];

    int N = in_sizes[0] / 64;
    int E = in_sizes[2] / 2;

    cudaFuncSetAttribute(edge_layer_kernel, cudaFuncAttributeMaxDynamicSharedMemorySize, SMEM_EDGE);
    cudaFuncSetAttribute(eps_edge_kernel, cudaFuncAttributeMaxDynamicSharedMemorySize, SMEM_EPS);
    cudaFuncSetAttribute(node_layer_kernel, cudaFuncAttributeMaxDynamicSharedMemorySize, SMEM_NODE);

    // normalize edge_index dtype (int32 vs int64) into g_ei32, clamped to [0,N)
    detect_kernel<<<1, 32>>>(ei_raw, 2 * E);
    convert_kernel<<<(2 * E + 255) / 256, 256>>>(ei_raw, 2 * E, N);

    // graph-safe init: kernels only
    init_kernel<<<(N + 255) / 256, 256>>>(N, x_in);

    // cudaGetSymbolAddress is a host API (not a stream op) — legal under capture.
    int* p_ei = nullptr;
    cudaGetSymbolAddress((void**)&p_ei, g_ei32);

    deg_kernel<<<(E + 255) / 256, 256>>>(p_ei + E, E);
    emb_kernel<<<(N + 63) / 64, 256, SMEM_EMB>>>(N, h_in, W_emb, b_emb);

    for (int i = 0; i < 3; i++) {
        clear_layer_kernel<<<(N * 32 + 255) / 256, 256>>>(N);
        edge_layer_kernel<<<(E + 63) / 64, 256, SMEM_EDGE>>>(
            p_ei, p_ei + E, E, Wm1 + (size_t)i * 257 * Hdim, bm1 + i * Hdim,
            Wm2 + (size_t)i * Hdim * Hdim, bm2 + i * Hdim,
            Wc1 + (size_t)i * Hdim * Hdim, bc1 + i * Hdim, Wc2 + i * Hdim);
        node_layer_kernel<<<(N + 31) / 32, 256, SMEM_NODE>>>(
            N, Wn1 + (size_t)i * 256 * Hdim, bn1 + i * Hdim,
            Wn2 + (size_t)i * Hdim * Hdim, bn2 + i * Hdim, lng + i * Hdim,
            lnb + i * Hdim);
    }

    eps_edge_kernel<<<(E + 63) / 64, 256, SMEM_EPS>>>(p_ei, p_ei + E, E, Wem1, bem1,
                                                      Wem2, bem2, Wec1, bec1,
                                                      Wec2, bec2);
    final_kernel<<<(N + 31) / 32, 256, SMEM_FINAL>>>(N, (float*)d_out, Wh1, bh1,
                                                     Wh2, bh2);
}

// round 15
// speedup vs baseline: 1.7539x; 1.7539x over previous
#include <cuda_runtime.h>
#include <math.h>

#define Hdim 128
#define NMAX 65536
#define EMAX 1048576

// ---------------- scratch (no cudaMalloc allowed) ----------------
__device__ float g_h[NMAX * Hdim];
__device__ float g_agg[NMAX * Hdim];
__device__ float g_P1[NMAX * Hdim];  // per-layer: h @ W_top + bias
__device__ float g_P2[NMAX * Hdim];  // per-layer: h @ W_mid
__device__ float g_x[NMAX * 3];
__device__ float g_coord[NMAX * 3];
__device__ float g_deg[NMAX];
__device__ float g_eps[NMAX * 3];
__device__ int g_ei32[2 * EMAX];
__device__ int g_mode;

__device__ __forceinline__ float silu_f(float v) { return v / (1.0f + __expf(-v)); }

// ---------------- edge-index dtype normalization (validated R14) ----------------
__global__ void detect_kernel(const void* __restrict__ p, int count) {
    if (threadIdx.x == 0 && blockIdx.x == 0) {
        const long long* q = (const long long*)p;
        int n = 64;
        if (n > count / 2) n = count / 2;
        int is64 = 1;
        for (int i = 0; i < n; i++) {
            unsigned long long v = (unsigned long long)q[i];
            if (v >> 32) { is64 = 0; break; }
        }
        g_mode = is64;
    }
}

__global__ void convert_kernel(const void* __restrict__ p, int count, int N) {
    int i = blockIdx.x * blockDim.x + threadIdx.x;
    if (i < count) {
        int v;
        if (g_mode) v = (int)((const long long*)p)[i];
        else        v = ((const int*)p)[i];
        if (v < 0) v = 0;
        if (v >= N) v = N - 1;
        g_ei32[i] = v;
    }
}

// ---------------- init / clear kernels ----------------
__global__ void init_kernel(int N, const float* __restrict__ x_in) {
    int i = blockIdx.x * blockDim.x + threadIdx.x;
    if (i < N) {
        g_deg[i] = 0.0f;
        g_eps[i * 3 + 0] = 0.0f; g_eps[i * 3 + 1] = 0.0f; g_eps[i * 3 + 2] = 0.0f;
        g_x[i * 3 + 0] = x_in[i * 3 + 0];
        g_x[i * 3 + 1] = x_in[i * 3 + 1];
        g_x[i * 3 + 2] = x_in[i * 3 + 2];
    }
}

__global__ void clear_layer_kernel(int N) {
    int i = blockIdx.x * blockDim.x + threadIdx.x;
    int n4 = N * 32;
    if (i < n4) ((float4*)g_agg)[i] = make_float4(0.f, 0.f, 0.f, 0.f);
    if (i < N) {
        g_coord[i * 3 + 0] = 0.0f; g_coord[i * 3 + 1] = 0.0f; g_coord[i * 3 + 2] = 0.0f;
    }
}

__global__ void deg_kernel(const int* __restrict__ ecol, int E) {
    int e = blockIdx.x * blockDim.x + threadIdx.x;
    if (e < E) atomicAdd(&g_deg[ecol[e]], 1.0f);
}

// ---------------- shared-memory tiled GEMM helper (validated R14) ----------------
template <int RPT>
__device__ __forceinline__ void gemm_accum(int K, int S, const float* sIn,
                                           const float* gW, float* sW,
                                           float (&acc)[RPT][8], int tx, int ty,
                                           int tid) {
    for (int kk = 0; kk < K; kk += 32) {
        const float4* src = (const float4*)(gW + (size_t)kk * Hdim);
        float4* dst = (float4*)sW;
#pragma unroll
        for (int t = 0; t < 4; t++) dst[tid + t * 256] = src[tid + t * 256];
        __syncthreads();
#pragma unroll
        for (int k4 = 0; k4 < 32; k4 += 4) {
            float av[RPT][4];
#pragma unroll
            for (int r = 0; r < RPT; r++) {
                float4 a = *(const float4*)&sIn[(ty * RPT + r) * S + kk + k4];
                av[r][0] = a.x; av[r][1] = a.y; av[r][2] = a.z; av[r][3] = a.w;
            }
#pragma unroll
            for (int j = 0; j < 4; j++) {
                float4 w0 = *(const float4*)&sW[(k4 + j) * Hdim + tx * 8];
                float4 w1 = *(const float4*)&sW[(k4 + j) * Hdim + tx * 8 + 4];
#pragma unroll
                for (int r = 0; r < RPT; r++) {
                    float c = av[r][j];
                    acc[r][0] = fmaf(c, w0.x, acc[r][0]);
                    acc[r][1] = fmaf(c, w0.y, acc[r][1]);
                    acc[r][2] = fmaf(c, w0.z, acc[r][2]);
                    acc[r][3] = fmaf(c, w0.w, acc[r][3]);
                    acc[r][4] = fmaf(c, w1.x, acc[r][4]);
                    acc[r][5] = fmaf(c, w1.y, acc[r][5]);
                    acc[r][6] = fmaf(c, w1.z, acc[r][6]);
                    acc[r][7] = fmaf(c, w1.w, acc[r][7]);
                }
            }
        }
        __syncthreads();
    }
}

// ---------------- embedding (validated R14) ----------------
__global__ __launch_bounds__(256) void emb_kernel(int N,
                                                  const float* __restrict__ hin,
                                                  const float* __restrict__ W,
                                                  const float* __restrict__ b) {
    extern __shared__ float sm[];
    float* s_in = sm;            // 64 x 68
    float* s_w = s_in + 64 * 68; // 32 x 128
    int tid = threadIdx.x;
    int tx = tid & 15, ty = tid >> 4;
    int n0 = blockIdx.x * 64;
    {
        int nl = tid >> 2, q = tid & 3;
        int n = n0 + nl; if (n >= N) n = N - 1;
        const float4* hp = (const float4*)(hin + (size_t)n * 64) + q * 4;
        float4* d0 = (float4*)(s_in + nl * 68 + q * 16);
#pragma unroll
        for (int t = 0; t < 4; t++) d0[t] = hp[t];
    }
    __syncthreads();
    float acc[4][8];
    {
        float bb[8];
#pragma unroll
        for (int j = 0; j < 8; j++) bb[j] = b[tx * 8 + j];
#pragma unroll
        for (int r = 0; r < 4; r++)
#pragma unroll
            for (int j = 0; j < 8; j++) acc[r][j] = bb[j];
    }
    gemm_accum<4>(64, 68, s_in, W, s_w, acc, tx, ty, tid);
#pragma unroll
    for (int r = 0; r < 4; r++) {
        int n = n0 + ty * 4 + r;
        if (n < N) {
#pragma unroll
            for (int j = 0; j < 8; j++) g_h[(size_t)n * Hdim + tx * 8 + j] = acc[r][j];
        }
    }
}

// ---------------- node-level precompute: out = g_h @ W (+bias) ----------------
// K=128, 64 nodes/block, 256 threads.
__global__ __launch_bounds__(256) void node_gemm_kernel(
    int N, const float* __restrict__ W, const float* __restrict__ b, int has_bias,
    float* __restrict__ out) {
    extern __shared__ float sm[];
    float* s_in = sm;             // 64 x 132
    float* s_w = s_in + 64 * 132; // 32 x 128
    int tid = threadIdx.x;
    int tx = tid & 15, ty = tid >> 4;
    int n0 = blockIdx.x * 64;
    {
        int nl = tid >> 2, q = tid & 3;
        int n = n0 + nl; if (n >= N) n = N - 1;
        const float4* hp = (const float4*)(g_h + (size_t)n * Hdim) + q * 8;
        float4* d0 = (float4*)(s_in + nl * 132 + q * 32);
#pragma unroll
        for (int t = 0; t < 8; t++) d0[t] = hp[t];
    }
    __syncthreads();
    float acc[4][8];
    {
        float bb[8];
#pragma unroll
        for (int j = 0; j < 8; j++) bb[j] = has_bias ? b[tx * 8 + j] : 0.0f;
#pragma unroll
        for (int r = 0; r < 4; r++)
#pragma unroll
            for (int j = 0; j < 8; j++) acc[r][j] = bb[j];
    }
    gemm_accum<4>(128, 132, s_in, W, s_w, acc, tx, ty, tid);
#pragma unroll
    for (int r = 0; r < 4; r++) {
        int n = n0 + ty * 4 + r;
        if (n < N) {
#pragma unroll
            for (int j = 0; j < 8; j++) out[(size_t)n * Hdim + tx * 8 + j] = acc[r][j];
        }
    }
}

// ---------------- fused per-layer edge kernel (GEMM1 eliminated) ----------------
// 64 edges/block, 256 threads. pre1 = silu(P1[row] + P2[col] + dist*Wm1_last)
__global__ __launch_bounds__(256) void edge_layer_kernel(
    const int* __restrict__ erow, const int* __restrict__ ecol, int E,
    const float* __restrict__ Wm1_last,
    const float* __restrict__ Wm2, const float* __restrict__ bm2,
    const float* __restrict__ Wc1, const float* __restrict__ bc1,
    const float* __restrict__ Wc2) {
    extern __shared__ float sm[];
    float* s_b1 = sm;                  // 64 x 132
    float* s_w = s_b1 + 64 * 132;      // 32 x 128
    float* s_b2 = s_w + 32 * Hdim;     // 64 x 132
    float* s_rel = s_b2 + 64 * 132;    // 64 x 4
    float* s_cm = s_rel + 256;         // 64
    int* s_col = (int*)(s_cm + 64);    // 64
    float* s_wl = (float*)(s_col + 64);// 128

    int tid = threadIdx.x;
    int tx = tid & 15, ty = tid >> 4;
    int e0 = blockIdx.x * 64;

    // Phase A: geometry + staging of the dist-row weights
    if (tid < 64) {
        int ee = e0 + tid; bool valid = (ee < E); if (!valid) ee = E - 1;
        int r = erow[ee], c = ecol[ee];
        float rx = g_x[r * 3 + 0] - g_x[c * 3 + 0];
        float ry = g_x[r * 3 + 1] - g_x[c * 3 + 1];
        float rz = g_x[r * 3 + 2] - g_x[c * 3 + 2];
        float dist = sqrtf(rx * rx + ry * ry + rz * rz);
        s_rel[tid * 4 + 0] = rx; s_rel[tid * 4 + 1] = ry;
        s_rel[tid * 4 + 2] = rz; s_rel[tid * 4 + 3] = dist;
        s_cm[tid] = 0.0f;
        s_col[tid] = valid ? c : -1;
    }
    if (tid >= 128) s_wl[tid - 128] = Wm1_last[tid - 128];
    __syncthreads();

    // Phase B: s_b1 = silu(P1[row] + P2[col] + dist * wl)
    {
        int el = tid & 63, q = tid >> 6;  // warp-contiguous el -> conflict-free STS
        int ee = e0 + el; if (ee >= E) ee = E - 1;
        int row = erow[ee], col = ecol[ee];
        float dist = s_rel[el * 4 + 3];
        const float4* p1 = (const float4*)(g_P1 + (size_t)row * Hdim) + q * 8;
        const float4* p2 = (const float4*)(g_P2 + (size_t)col * Hdim) + q * 8;
        const float4* wl = (const float4*)(s_wl) + q * 8;
        float4* dstp = (float4*)(s_b1 + el * 132 + q * 32);
#pragma unroll
        for (int t = 0; t < 8; t++) {
            float4 a = p1[t], b = p2[t], w = wl[t], v;
            v.x = silu_f(a.x + b.x + dist * w.x);
            v.y = silu_f(a.y + b.y + dist * w.y);
            v.z = silu_f(a.z + b.z + dist * w.z);
            v.w = silu_f(a.w + b.w + dist * w.w);
            dstp[t] = v;
        }
    }
    __syncthreads();

    float acc[4][8];
    // --- GEMM2: m = silu(out1 @ Wm2 + bm2), scatter into agg
    {
        float bb[8];
#pragma unroll
        for (int j = 0; j < 8; j++) bb[j] = bm2[tx * 8 + j];
#pragma unroll
        for (int r = 0; r < 4; r++)
#pragma unroll
            for (int j = 0; j < 8; j++) acc[r][j] = bb[j];
    }
    gemm_accum<4>(128, 132, s_b1, Wm2, s_w, acc, tx, ty, tid);
#pragma unroll
    for (int r = 0; r < 4; r++) {
        float mv[8];
#pragma unroll
        for (int j = 0; j < 8; j++) mv[j] = silu_f(acc[r][j]);
        float4 v0 = {mv[0], mv[1], mv[2], mv[3]};
        float4 v1 = {mv[4], mv[5], mv[6], mv[7]};
        *(float4*)&s_b2[(ty * 4 + r) * 132 + tx * 8] = v0;
        *(float4*)&s_b2[(ty * 4 + r) * 132 + tx * 8 + 4] = v1;
        int c = s_col[ty * 4 + r];
        if (c >= 0) {
            float* base = g_agg + (size_t)c * Hdim + tx * 8;
#pragma unroll
            for (int j = 0; j < 8; j++) atomicAdd(base + j, mv[j]);
        }
    }
    // --- GEMM3: c1 = silu(m @ Wc1 + bc1); coord_mult = tanh(c1 . Wc2)
    {
        float bb[8];
#pragma unroll
        for (int j = 0; j < 8; j++) bb[j] = bc1[tx * 8 + j];
#pragma unroll
        for (int r = 0; r < 4; r++)
#pragma unroll
            for (int j = 0; j < 8; j++) acc[r][j] = bb[j];
    }
    gemm_accum<4>(128, 132, s_b2, Wc1, s_w, acc, tx, ty, tid);
    {
        float wc[8];
#pragma unroll
        for (int j = 0; j < 8; j++) wc[j] = Wc2[tx * 8 + j];
#pragma unroll
        for (int r = 0; r < 4; r++) {
            float p = 0.0f;
#pragma unroll
            for (int j = 0; j < 8; j++) p = fmaf(silu_f(acc[r][j]), wc[j], p);
            atomicAdd(&s_cm[ty * 4 + r], p);
        }
    }
    __syncthreads();
    if (tid < 64) {
        int c = s_col[tid];
        if (c >= 0) {
            float cm = tanhf(s_cm[tid]);
            float inv = 1.0f / (s_rel[tid * 4 + 3] + 1e-8f);
            float s = cm * inv;
#pragma unroll
            for (int d = 0; d < 3; d++)
                atomicAdd(&g_coord[(size_t)c * 3 + d], s * s_rel[tid * 4 + d]);
        }
    }
}

// ---------------- per-layer node kernel (validated R14) ----------------
__global__ __launch_bounds__(256) void node_layer_kernel(
    int N, const float* __restrict__ Wn1, const float* __restrict__ bn1,
    const float* __restrict__ Wn2, const float* __restrict__ bn2,
    const float* __restrict__ lng, const float* __restrict__ lnb) {
    extern __shared__ float sm[];
    float* s_nu = sm;              // 32 x 256
    float* s_w = s_nu + 32 * 256;  // 32 x 128
    float* s_t = s_w + 32 * Hdim;  // 32 x 132
    int tid = threadIdx.x;
    int tx = tid & 15, ty = tid >> 4;
    int n0 = blockIdx.x * 32;

    if (tid < 32) {
        int n = n0 + tid;
        if (n < N) {
            float inv = 1.0f / (g_deg[n] + 1.0f);
#pragma unroll
            for (int d = 0; d < 3; d++)
                g_x[(size_t)n * 3 + d] += g_coord[(size_t)n * 3 + d] * inv;
        }
    }
    {
        int nl = tid >> 3, p = tid & 7;
        int n = n0 + nl; if (n >= N) n = N - 1;
        const float4* hp = (const float4*)(g_h + (size_t)n * Hdim) + p * 4;
        const float4* ap = (const float4*)(g_agg + (size_t)n * Hdim) + p * 4;
        float4* d0 = (float4*)(s_nu + nl * 256 + p * 16);
        float4* d1 = (float4*)(s_nu + nl * 256 + 128 + p * 16);
#pragma unroll
        for (int t = 0; t < 4; t++) { d0[t] = hp[t]; d1[t] = ap[t]; }
    }
    __syncthreads();

    float acc[2][8];
    {
        float bb[8];
#pragma unroll
        for (int j = 0; j < 8; j++) bb[j] = bn1[tx * 8 + j];
#pragma unroll
        for (int r = 0; r < 2; r++)
#pragma unroll
            for (int j = 0; j < 8; j++) acc[r][j] = bb[j];
    }
    gemm_accum<2>(256, 256, s_nu, Wn1, s_w, acc, tx, ty, tid);
#pragma unroll
    for (int r = 0; r < 2; r++) {
        float4 v0, v1;
        v0.x = silu_f(acc[r][0]); v0.y = silu_f(acc[r][1]);
        v0.z = silu_f(acc[r][2]); v0.w = silu_f(acc[r][3]);
        v1.x = silu_f(acc[r][4]); v1.y = silu_f(acc[r][5]);
        v1.z = silu_f(acc[r][6]); v1.w = silu_f(acc[r][7]);
        *(float4*)&s_t[(ty * 2 + r) * 132 + tx * 8] = v0;
        *(float4*)&s_t[(ty * 2 + r) * 132 + tx * 8 + 4] = v1;
    }
    {
        float bb[8];
#pragma unroll
        for (int j = 0; j < 8; j++) bb[j] = bn2[tx * 8 + j];
#pragma unroll
        for (int r = 0; r < 2; r++)
#pragma unroll
            for (int j = 0; j < 8; j++) acc[r][j] = bb[j];
    }
    gemm_accum<2>(128, 132, s_t, Wn2, s_w, acc, tx, ty, tid);
#pragma unroll
    for (int r = 0; r < 2; r++)
#pragma unroll
        for (int j = 0; j < 8; j++)
            s_nu[(ty * 2 + r) * 256 + tx * 8 + j] += acc[r][j];
    __syncthreads();
    int wid = tid >> 5, lane = tid & 31;
#pragma unroll
    for (int k = 0; k < 4; k++) {
        int nl = wid * 4 + k;
        int n = n0 + nl;
        float v[4];
#pragma unroll
        for (int t = 0; t < 4; t++) v[t] = s_nu[nl * 256 + lane * 4 + t];
        float s = v[0] + v[1] + v[2] + v[3];
#pragma unroll
        for (int o = 16; o > 0; o >>= 1) s += __shfl_xor_sync(0xffffffffu, s, o);
        float mu = s * (1.0f / 128.0f);
        float q = 0.0f;
#pragma unroll
        for (int t = 0; t < 4; t++) { float d = v[t] - mu; q = fmaf(d, d, q); }
#pragma unroll
        for (int o = 16; o > 0; o >>= 1) q += __shfl_xor_sync(0xffffffffu, q, o);
        float rs = rsqrtf(q * (1.0f / 128.0f) + 1e-5f);
        if (n < N) {
#pragma unroll
            for (int t = 0; t < 4; t++) {
                int f = lane * 4 + t;
                g_h[(size_t)n * Hdim + f] = (v[t] - mu) * rs * lng[f] + lnb[f];
            }
        }
    }
}

// ---------------- epsilon edge head (GEMM1 eliminated) ----------------
// pre = silu(Q1[row] + Q2[col] + rel@W4[0:3] + dist*W4[3]);  W4 = Wem1 rows 256..259
__global__ __launch_bounds__(256) void eps_edge_kernel(
    const int* __restrict__ erow, const int* __restrict__ ecol, int E,
    const float* __restrict__ W4,
    const float* __restrict__ Wem2, const float* __restrict__ bem2,
    const float* __restrict__ Wec1, const float* __restrict__ bec1,
    const float* __restrict__ Wec2, const float* __restrict__ bec2) {
    extern __shared__ float sm[];
    float* s_b1 = sm;                  // 64 x 132
    float* s_w = s_b1 + 64 * 132;      // 32 x 128
    float* s_b2 = s_w + 32 * Hdim;     // 64 x 132
    float* s_rel = s_b2 + 64 * 132;    // 64 x 4
    float* s_eps = s_rel + 256;        // 64 x 3
    int* s_col = (int*)(s_eps + 192);  // 64
    float* s_w4 = (float*)(s_col + 64);// 4 x 128

    int tid = threadIdx.x;
    int tx = tid & 15, ty = tid >> 4;
    int e0 = blockIdx.x * 64;

    if (tid < 64) {
        int ee = e0 + tid; bool valid = (ee < E); if (!valid) ee = E - 1;
        int r = erow[ee], c = ecol[ee];
        float rx = g_x[r * 3 + 0] - g_x[c * 3 + 0];
        float ry = g_x[r * 3 + 1] - g_x[c * 3 + 1];
        float rz = g_x[r * 3 + 2] - g_x[c * 3 + 2];
        float dist = sqrtf(rx * rx + ry * ry + rz * rz);
        s_rel[tid * 4 + 0] = rx; s_rel[tid * 4 + 1] = ry;
        s_rel[tid * 4 + 2] = rz; s_rel[tid * 4 + 3] = dist;
        s_eps[tid * 3 + 0] = 0.0f; s_eps[tid * 3 + 1] = 0.0f; s_eps[tid * 3 + 2] = 0.0f;
        s_col[tid] = valid ? c : -1;
    }
    s_w4[tid] = W4[tid];
    s_w4[tid + 256] = W4[tid + 256];
    __syncthreads();

    // Phase B: s_b1 = silu(Q1[row] + Q2[col] + rx*w0 + ry*w1 + rz*w2 + dist*w3)
    {
        int el = tid & 63, q = tid >> 6;
        int ee = e0 + el; if (ee >= E) ee = E - 1;
        int row = erow[ee], col = ecol[ee];
        float rx = s_rel[el * 4 + 0], ry = s_rel[el * 4 + 1];
        float rz = s_rel[el * 4 + 2], dd = s_rel[el * 4 + 3];
        const float4* p1 = (const float4*)(g_P1 + (size_t)row * Hdim) + q * 8;
        const float4* p2 = (const float4*)(g_P2 + (size_t)col * Hdim) + q * 8;
        const float4* w0p = (const float4*)(s_w4) + q * 8;
        const float4* w1p = (const float4*)(s_w4 + 128) + q * 8;
        const float4* w2p = (const float4*)(s_w4 + 256) + q * 8;
        const float4* w3p = (const float4*)(s_w4 + 384) + q * 8;
        float4* dstp = (float4*)(s_b1 + el * 132 + q * 32);
#pragma unroll
        for (int t = 0; t < 8; t++) {
            float4 a = p1[t], b = p2[t];
            float4 w0 = w0p[t], w1 = w1p[t], w2 = w2p[t], w3 = w3p[t];
            float4 v;
            v.x = silu_f(fmaf(dd, w3.x, fmaf(rz, w2.x, fmaf(ry, w1.x, fmaf(rx, w0.x, a.x + b.x)))));
            v.y = silu_f(fmaf(dd, w3.y, fmaf(rz, w2.y, fmaf(ry, w1.y, fmaf(rx, w0.y, a.y + b.y)))));
            v.z = silu_f(fmaf(dd, w3.z, fmaf(rz, w2.z, fmaf(ry, w1.z, fmaf(rx, w0.z, a.z + b.z)))));
            v.w = silu_f(fmaf(dd, w3.w, fmaf(rz, w2.w, fmaf(ry, w1.w, fmaf(rx, w0.w, a.w + b.w)))));
            dstp[t] = v;
        }
    }
    __syncthreads();

    float acc[4][8];
    // em = silu(pre @ Wem2 + bem2)
    {
        float bb[8];
#pragma unroll
        for (int j = 0; j < 8; j++) bb[j] = bem2[tx * 8 + j];
#pragma unroll
        for (int r = 0; r < 4; r++)
#pragma unroll
            for (int j = 0; j < 8; j++) acc[r][j] = bb[j];
    }
    gemm_accum<4>(128, 132, s_b1, Wem2, s_w, acc, tx, ty, tid);
#pragma unroll
    for (int r = 0; r < 4; r++) {
        float4 v0, v1;
        v0.x = silu_f(acc[r][0]); v0.y = silu_f(acc[r][1]);
        v0.z = silu_f(acc[r][2]); v0.w = silu_f(acc[r][3]);
        v1.x = silu_f(acc[r][4]); v1.y = silu_f(acc[r][5]);
        v1.z = silu_f(acc[r][6]); v1.w = silu_f(acc[r][7]);
        *(float4*)&s_b2[(ty * 4 + r) * 132 + tx * 8] = v0;
        *(float4*)&s_b2[(ty * 4 + r) * 132 + tx * 8 + 4] = v1;
    }
    // eps_src = silu(em @ Wec1 + bec1) @ Wec2
    {
        float bb[8];
#pragma unroll
        for (int j = 0; j < 8; j++) bb[j] = bec1[tx * 8 + j];
#pragma unroll
        for (int r = 0; r < 4; r++)
#pragma unroll
            for (int j = 0; j < 8; j++) acc[r][j] = bb[j];
    }
    gemm_accum<4>(128, 132, s_b2, Wec1, s_w, acc, tx, ty, tid);
    {
        float wr[8][3];
#pragma unroll
        for (int j = 0; j < 8; j++)
#pragma unroll
            for (int d = 0; d < 3; d++) wr[j][d] = Wec2[(tx * 8 + j) * 3 + d];
#pragma unroll
        for (int r = 0; r < 4; r++) {
            float p0 = 0.0f, p1 = 0.0f, p2 = 0.0f;
#pragma unroll
            for (int j = 0; j < 8; j++) {
                float t = silu_f(acc[r][j]);
                p0 = fmaf(t, wr[j][0], p0);
                p1 = fmaf(t, wr[j][1], p1);
                p2 = fmaf(t, wr[j][2], p2);
            }
            atomicAdd(&s_eps[(ty * 4 + r) * 3 + 0], p0);
            atomicAdd(&s_eps[(ty * 4 + r) * 3 + 1], p1);
            atomicAdd(&s_eps[(ty * 4 + r) * 3 + 2], p2);
        }
    }
    __syncthreads();
    if (tid < 64) {
        int c = s_col[tid];
        if (c >= 0) {
#pragma unroll
            for (int d = 0; d < 3; d++)
                atomicAdd(&g_eps[(size_t)c * 3 + d], s_eps[tid * 3 + d] + bec2[d]);
        }
    }
}

// ---------------- final node head + output writeback (validated R14) ----------------
__global__ __launch_bounds__(256) void final_kernel(int N, float* __restrict__ out,
                                                    const float* __restrict__ Wh1,
                                                    const float* __restrict__ bh1,
                                                    const float* __restrict__ Wh2,
                                                    const float* __restrict__ bh2) {
    extern __shared__ float sm[];
    float* s_hx = sm;              // 32 x 132
    float* s_w = s_hx + 32 * 132;  // 32 x 128
    float* s_o = s_w + 32 * Hdim;  // 32 x 3
    int tid = threadIdx.x;
    int tx = tid & 15, ty = tid >> 4;
    int n0 = blockIdx.x * 32;

    {
        int nl = tid >> 3, p = tid & 7;
        int n = n0 + nl; bool v = (n < N); int nn = v ? n : N - 1;
        const float4* hp = (const float4*)(g_h + (size_t)nn * Hdim) + p * 4;
        float4* d0 = (float4*)(s_hx + nl * 132 + p * 16);
        float4* o = (float4*)(out + (size_t)nn * Hdim) + p * 4;
#pragma unroll
        for (int t = 0; t < 4; t++) { float4 vv = hp[t]; d0[t] = vv; if (v) o[t] = vv; }
    }
    if (tid < 32) {
        int n = n0 + tid; bool v = (n < N); int nn = v ? n : N - 1;
#pragma unroll
        for (int d = 0; d < 3; d++) {
            float xv = g_x[(size_t)nn * 3 + d];
            s_hx[tid * 132 + 128 + d] = xv;
            if (v) out[(size_t)N * Hdim + (size_t)nn * 3 + d] = xv;
        }
        s_o[tid * 3 + 0] = 0.0f; s_o[tid * 3 + 1] = 0.0f; s_o[tid * 3 + 2] = 0.0f;
    }
    __syncthreads();

    float acc[2][8];
    {
        float bb[8], w0[8], w1[8], w2[8];
#pragma unroll
        for (int j = 0; j < 8; j++) {
            bb[j] = bh1[tx * 8 + j];
            w0[j] = Wh1[128 * Hdim + tx * 8 + j];
            w1[j] = Wh1[129 * Hdim + tx * 8 + j];
            w2[j] = Wh1[130 * Hdim + tx * 8 + j];
        }
#pragma unroll
        for (int r = 0; r < 2; r++) {
            int nl = ty * 2 + r;
            float x0 = s_hx[nl * 132 + 128];
            float x1 = s_hx[nl * 132 + 129];
            float x2 = s_hx[nl * 132 + 130];
#pragma unroll
            for (int j = 0; j < 8; j++) {
                float a = fmaf(x0, w0[j], bb[j]);
                a = fmaf(x1, w1[j], a);
                acc[r][j] = fmaf(x2, w2[j], a);
            }
        }
    }
    gemm_accum<2>(128, 132, s_hx, Wh1, s_w, acc, tx, ty, tid);
    {
        float wr[8][3];
#pragma unroll
        for (int j = 0; j < 8; j++)
#pragma unroll
            for (int d = 0; d < 3; d++) wr[j][d] = Wh2[(tx * 8 + j) * 3 + d];
#pragma unroll
        for (int r = 0; r < 2; r++) {
            float p0 = 0.0f, p1 = 0.0f, p2 = 0.0f;
#pragma unroll
            for (int j = 0; j < 8; j++) {
                float t = silu_f(acc[r][j]);
                p0 = fmaf(t, wr[j][0], p0);
                p1 = fmaf(t, wr[j][1], p1);
                p2 = fmaf(t, wr[j][2], p2);
            }
            atomicAdd(&s_o[(ty * 2 + r) * 3 + 0], p0);
            atomicAdd(&s_o[(ty * 2 + r) * 3 + 1], p1);
            atomicAdd(&s_o[(ty * 2 + r) * 3 + 2], p2);
        }
    }
    __syncthreads();
    if (tid < 96) {
        int nl = tid / 3, d = tid % 3;
        int n = n0 + nl;
        if (n < N)
            out[(size_t)N * Hdim + (size_t)N * 3 + (size_t)n * 3 + d] =
                g_eps[(size_t)n * 3 + d] + s_o[tid] + bh2[d];
    }
}

// ---------------- host launcher ----------------
#define SMEM_EDGE ((64 * 132 + 32 * 128 + 64 * 132 + 64 * 4 + 64 + 64 + 128) * 4)
#define SMEM_EPS ((64 * 132 + 32 * 128 + 64 * 132 + 64 * 4 + 64 * 3 + 64 + 512) * 4)
#define SMEM_NODE ((32 * 256 + 32 * 128 + 32 * 132) * 4)
#define SMEM_EMB ((64 * 68 + 32 * 128) * 4)
#define SMEM_NG ((64 * 132 + 32 * 128) * 4)
#define SMEM_FINAL ((32 * 132 + 32 * 128 + 32 * 3) * 4)

extern "C" void kernel_launch(void* const* d_in, const int* in_sizes, int n_in,
                              void* d_out, int out_size) {
    const float* h_in = (const float*)d_in[0];
    const float* x_in = (const float*)d_in[1];
    const void* ei_raw = d_in[2];
    const float* W_emb = (const float*)d_in[3];
    const float* b_emb = (const float*)d_in[4];
    const float* Wm1 = (const float*)d_in[5];
    const float* bm1 = (const float*)d_in[6];
    const float* Wm2 = (const float*)d_in[7];
    const float* bm2 = (const float*)d_in[8];
    const float* Wc1 = (const float*)d_in[9];
    const float* bc1 = (const float*)d_in[10];
    const float* Wc2 = (const float*)d_in[11];
    const float* Wn1 = (const float*)d_in[12];
    const float* bn1 = (const float*)d_in[13];
    const float* Wn2 = (const float*)d_in[14];
    const float* bn2 = (const float*)d_in[15];
    const float* lng = (const float*)d_in[16];
    const float* lnb = (const float*)d_in[17];
    const float* Wem1 = (const float*)d_in[18];
    const float* bem1 = (const float*)d_in[19];
    const float* Wem2 = (const float*)d_in[20];
    const float* bem2 = (const float*)d_in[21];
    const float* Wec1 = (const float*)d_in[22];
    const float* bec1 = (const float*)d_in[23];
    const float* Wec2 = (const float*)d_in[24];
    const float* bec2 = (const float*)d_in[25];
    const float* Wh1 = (const float*)d_in[26];
    const float* bh1 = (const float*)d_in[27];
    const float* Wh2 = (const float*)d_in[28];
    const float* bh2 = (const float*)d_in[29];

    int N = in_sizes[0] / 64;
    int E = in_sizes[2] / 2;

    cudaFuncSetAttribute(edge_layer_kernel, cudaFuncAttributeMaxDynamicSharedMemorySize, SMEM_EDGE);
    cudaFuncSetAttribute(eps_edge_kernel, cudaFuncAttributeMaxDynamicSharedMemorySize, SMEM_EPS);
    cudaFuncSetAttribute(node_layer_kernel, cudaFuncAttributeMaxDynamicSharedMemorySize, SMEM_NODE);
    cudaFuncSetAttribute(node_gemm_kernel, cudaFuncAttributeMaxDynamicSharedMemorySize, SMEM_NG);

    detect_kernel<<<1, 32>>>(ei_raw, 2 * E);
    convert_kernel<<<(2 * E + 255) / 256, 256>>>(ei_raw, 2 * E, N);
    init_kernel<<<(N + 255) / 256, 256>>>(N, x_in);

    int* p_ei = nullptr;
    float *p_P1 = nullptr, *p_P2 = nullptr;
    cudaGetSymbolAddress((void**)&p_ei, g_ei32);
    cudaGetSymbolAddress((void**)&p_P1, g_P1);
    cudaGetSymbolAddress((void**)&p_P2, g_P2);

    deg_kernel<<<(E + 255) / 256, 256>>>(p_ei + E, E);
    emb_kernel<<<(N + 63) / 64, 256, SMEM_EMB>>>(N, h_in, W_emb, b_emb);

    int ngrid = (N + 63) / 64;
    for (int i = 0; i < 3; i++) {
        const float* Wm1i = Wm1 + (size_t)i * 257 * Hdim;
        clear_layer_kernel<<<(N * 32 + 255) / 256, 256>>>(N);
        node_gemm_kernel<<<ngrid, 256, SMEM_NG>>>(N, Wm1i, bm1 + i * Hdim, 1, p_P1);
        node_gemm_kernel<<<ngrid, 256, SMEM_NG>>>(N, Wm1i + 128 * Hdim, nullptr, 0, p_P2);
        edge_layer_kernel<<<(E + 63) / 64, 256, SMEM_EDGE>>>(
            p_ei, p_ei + E, E, Wm1i + 256 * Hdim,
            Wm2 + (size_t)i * Hdim * Hdim, bm2 + i * Hdim,
            Wc1 + (size_t)i * Hdim * Hdim, bc1 + i * Hdim, Wc2 + i * Hdim);
        node_layer_kernel<<<(N + 31) / 32, 256, SMEM_NODE>>>(
            N, Wn1 + (size_t)i * 256 * Hdim, bn1 + i * Hdim,
            Wn2 + (size_t)i * Hdim * Hdim, bn2 + i * Hdim, lng + i * Hdim,
            lnb + i * Hdim);
    }

    node_gemm_kernel<<<ngrid, 256, SMEM_NG>>>(N, Wem1, bem1, 1, p_P1);
    node_gemm_kernel<<<ngrid, 256, SMEM_NG>>>(N, Wem1 + 128 * Hdim, nullptr, 0, p_P2);
    eps_edge_kernel<<<(E + 63) / 64, 256, SMEM_EPS>>>(p_ei, p_ei + E, E,
                                                      Wem1 + 256 * Hdim, Wem2, bem2,
                                                      Wec1, bec1, Wec2, bec2);
    final_kernel<<<(N + 31) / 32, 256, SMEM_FINAL>>>(N, (float*)d_out, Wh1, bh1,
                                                     Wh2, bh2);
}